// round 12
// baseline (speedup 1.0000x reference)
#include <cuda_runtime.h>
#include <cstdint>

#define BB 4
#define C1 256
#define MID 64
#define HW 56
#define PP 3136       // 56*56
#define NPX 12544     // BB*PP
#define W2O 784       // 49*16
#define BN_EPS 1e-3f

typedef unsigned long long ull;

// Intermediates
__device__ float g_y[NPX * MID];          // pixel-major y[bp][m], tf32-rounded
__device__ float g_w2t[16 * 64 * 56];     // w2t [g][k][o_pad56], BN2-scaled, tf32
__device__ float g_sh2[W2O];              // BN2 shift

// ---------------------------------------------------------------------------
__device__ __forceinline__ uint32_t f2tf(float f) {
    uint32_t u;
    asm("cvt.rna.tf32.f32 %0, %1;" : "=r"(u) : "f"(f));
    return u;
}
__device__ __forceinline__ float4 cvt4(float4 v) {
    v.x = __uint_as_float(f2tf(v.x));
    v.y = __uint_as_float(f2tf(v.y));
    v.z = __uint_as_float(f2tf(v.z));
    v.w = __uint_as_float(f2tf(v.w));
    return v;
}
__device__ __forceinline__ void mma_tf32(float* c, uint32_t a0, uint32_t a1,
                                         uint32_t a2, uint32_t a3,
                                         uint32_t b0, uint32_t b1) {
    asm volatile(
        "mma.sync.aligned.m16n8k8.row.col.f32.tf32.tf32.f32 "
        "{%0,%1,%2,%3}, {%4,%5,%6,%7}, {%8,%9}, {%0,%1,%2,%3};\n"
        : "+f"(c[0]), "+f"(c[1]), "+f"(c[2]), "+f"(c[3])
        : "r"(a0), "r"(a1), "r"(a2), "r"(a3), "r"(b0), "r"(b1));
}
__device__ __forceinline__ float aconf(float v, float d12, float p2, float bet) {
    const float d = d12 * v;
    const float sig = 1.0f / (1.0f + __expf(-bet * d));
    return d * sig + p2 * v;
}
// cp.async 16B with zero-fill on !pred
__device__ __forceinline__ void cp16(uint32_t dst, const void* src, bool pred) {
    const int sz = pred ? 16 : 0;
    asm volatile("cp.async.cg.shared.global [%0], [%1], 16, %2;\n"
                 :: "r"(dst), "l"(src), "r"(sz));
}
// packed f32x2 helpers
__device__ __forceinline__ ull pack2(float lo, float hi) {
    ull r;
    asm("mov.b64 %0, {%1, %2};" : "=l"(r) : "f"(lo), "f"(hi));
    return r;
}
__device__ __forceinline__ void fma2(ull& d, ull a, ull b) {
    asm("fma.rn.f32x2 %0, %1, %2, %0;" : "+l"(d) : "l"(a), "l"(b));
}

// ---------------------------------------------------------------------------
// Kernel 1 (tf32 MMA, double-buffered) + folded w2-prep blocks.
// Blocks [0,392): y GEMM; [392,588): w2t prep + sh2.
// ---------------------------------------------------------------------------
__global__ __launch_bounds__(128) void k1_conv1_bn_acon(
    const float* __restrict__ x, const float* __restrict__ w1,
    const float* __restrict__ g1, const float* __restrict__ b1,
    const float* __restrict__ mu1, const float* __restrict__ v1,
    const float* __restrict__ ap1, const float* __restrict__ ap2,
    const float* __restrict__ ab,
    const float* __restrict__ w2,
    const float* __restrict__ g2, const float* __restrict__ b2,
    const float* __restrict__ mu2, const float* __restrict__ v2)
{
    __shared__ float xs[2][32][40];
    __shared__ float ws[2][64][36];

    const int tid = threadIdx.x;

    if (blockIdx.x >= 392) {
        const int p = blockIdx.x - 392;
        const int k = tid & 63;
        #pragma unroll
        for (int i = 0; i < 2; ++i) {
            const int o  = p * 4 + (tid >> 6) + i * 2;
            const int g  = o / 49;
            const int ol = o - g * 49;
            const float s = g2[o] * rsqrtf(v2[o] + BN_EPS);
            g_w2t[g * 3584 + k * 56 + ol] =
                __uint_as_float(f2tf(w2[o * MID + k] * s));
            if (k == 0) g_sh2[o] = b2[o] - mu2[o] * s;
        }
        return;
    }

    const int wrp  = tid >> 5;
    const int lane = tid & 31;
    const int g    = lane >> 2;
    const int tig  = lane & 3;
    const int pxg  = wrp & 1;
    const int nh   = wrp >> 1;

    const int b  = blockIdx.x / 98;
    const int p0 = (blockIdx.x % 98) * 32;
    const float* xb = x + (size_t)b * C1 * PP + p0;

    float4 xv[2], wv[4];

    #pragma unroll
    for (int it = 0; it < 2; ++it) {
        const int f = tid + 128 * it, k = f >> 3, q = f & 7;
        xv[it] = *(const float4*)&xb[(size_t)k * PP + q * 4];
    }
    #pragma unroll
    for (int it = 0; it < 4; ++it) {
        const int f = tid + 128 * it, m = f >> 3, q = f & 7;
        wv[it] = *(const float4*)&w1[m * C1 + q * 4];
    }
    #pragma unroll
    for (int it = 0; it < 2; ++it) {
        const int f = tid + 128 * it, k = f >> 3, q = f & 7;
        *(float4*)&xs[0][k][q * 4] = cvt4(xv[it]);
    }
    #pragma unroll
    for (int it = 0; it < 4; ++it) {
        const int f = tid + 128 * it, m = f >> 3, q = f & 7;
        *(float4*)&ws[0][m][q * 4] = cvt4(wv[it]);
    }
    __syncthreads();

    float acc[4][4] = {};
    const int pxr = pxg * 16 + g;

    for (int kc = 0; kc < 8; ++kc) {
        if (kc < 7) {
            const int k0n = (kc + 1) * 32;
            #pragma unroll
            for (int it = 0; it < 2; ++it) {
                const int f = tid + 128 * it, k = f >> 3, q = f & 7;
                xv[it] = *(const float4*)&xb[(size_t)(k0n + k) * PP + q * 4];
            }
            #pragma unroll
            for (int it = 0; it < 4; ++it) {
                const int f = tid + 128 * it, m = f >> 3, q = f & 7;
                wv[it] = *(const float4*)&w1[m * C1 + k0n + q * 4];
            }
        }
        const int buf = kc & 1;
        #pragma unroll
        for (int ks = 0; ks < 4; ++ks) {
            const int kb = ks * 8;
            const uint32_t a0 = __float_as_uint(xs[buf][kb + tig    ][pxr]);
            const uint32_t a1 = __float_as_uint(xs[buf][kb + tig    ][pxr + 8]);
            const uint32_t a2 = __float_as_uint(xs[buf][kb + tig + 4][pxr]);
            const uint32_t a3 = __float_as_uint(xs[buf][kb + tig + 4][pxr + 8]);
            #pragma unroll
            for (int j = 0; j < 4; ++j) {
                const int m = nh * 32 + j * 8 + g;
                const uint32_t b0 = __float_as_uint(ws[buf][m][kb + tig]);
                const uint32_t b1 = __float_as_uint(ws[buf][m][kb + tig + 4]);
                mma_tf32(acc[j], a0, a1, a2, a3, b0, b1);
            }
        }
        __syncthreads();
        if (kc < 7) {
            const int nb = (kc + 1) & 1;
            #pragma unroll
            for (int it = 0; it < 2; ++it) {
                const int f = tid + 128 * it, k = f >> 3, q = f & 7;
                *(float4*)&xs[nb][k][q * 4] = cvt4(xv[it]);
            }
            #pragma unroll
            for (int it = 0; it < 4; ++it) {
                const int f = tid + 128 * it, m = f >> 3, q = f & 7;
                *(float4*)&ws[nb][m][q * 4] = cvt4(wv[it]);
            }
            __syncthreads();
        }
    }

    const size_t bp0 = (size_t)b * PP + p0;
    #pragma unroll
    for (int j = 0; j < 4; ++j) {
        const int ma = nh * 32 + j * 8 + 2 * tig;
        const int mb = ma + 1;
        const float sA  = g1[ma] * rsqrtf(v1[ma] + BN_EPS);
        const float shA = b1[ma] - mu1[ma] * sA;
        const float sB  = g1[mb] * rsqrtf(v1[mb] + BN_EPS);
        const float shB = b1[mb] - mu1[mb] * sB;
        const float dA = ap1[ma] - ap2[ma], pA = ap2[ma], bA = ab[ma];
        const float dB = ap1[mb] - ap2[mb], pB = ap2[mb], bB = ab[mb];

        float2 o01, o23;
        o01.x = __uint_as_float(f2tf(aconf(acc[j][0] * sA + shA, dA, pA, bA)));
        o01.y = __uint_as_float(f2tf(aconf(acc[j][1] * sB + shB, dB, pB, bB)));
        o23.x = __uint_as_float(f2tf(aconf(acc[j][2] * sA + shA, dA, pA, bA)));
        o23.y = __uint_as_float(f2tf(aconf(acc[j][3] * sB + shB, dB, pB, bB)));

        *(float2*)&g_y[(bp0 + pxr    ) * MID + ma] = o01;
        *(float2*)&g_y[(bp0 + pxr + 8) * MID + ma] = o23;
    }
}

// ---------------------------------------------------------------------------
// Kernel 23 (fused, v9 = R11 + f32x2 packed involution).
// Pool: ys[64][68] | w2s[2][64][56] | xsm[32][228]; wsm overlays ys+w2s.
// ---------------------------------------------------------------------------
#define YS_OFF   0
#define W2S_OFF  (64 * 68)                  // 4352
#define XSM_OFF  (W2S_OFF + 2 * 64 * 56)    // 11520
#define XC_STR   228                        // mod 32 = 4 -> conflict-free f4
#define WSM_STR  3332                       // 49*68 per group
#define POOL_FLOATS (XSM_OFF + 32 * XC_STR) // 18816 -> 75264 B

__global__ __launch_bounds__(256, 3) void k23_fused(
    const float* __restrict__ x, float* __restrict__ out)
{
    extern __shared__ float pool[];
    float* ys  = pool + YS_OFF;      // [px][68]
    float* w2s = pool + W2S_OFF;     // [grp][k][56]
    float* xsm = pool + XSM_OFF;     // [ch][14][16] window w0-4..w0+11
    float* wsm = pool + YS_OFF;      // phase B: [grp][49][68]

    const int tid  = threadIdx.x;
    const int wrp  = tid >> 5;
    const int lane = tid & 31;
    const int g    = lane >> 2;
    const int tig  = lane & 3;

    const int t   = blockIdx.x;
    const int gr0 = blockIdx.y * 2;
    const int b   = blockIdx.z;
    const int h0  = (t / 7) * 8;
    const int w0  = (t % 7) * 8;

    const uint32_t smem_base = (uint32_t)__cvta_generic_to_shared(pool);

    // ---- Phase A group 0: y tile + 2 w2t slices
    #pragma unroll
    for (int it = 0; it < 4; ++it) {
        const int f = tid + 256 * it;            // 0..1023
        const int row = f >> 7;
        const int q   = f & 127;
        const size_t bp = (size_t)b * PP + (h0 + row) * HW + w0;
        const int pxl = row * 8 + (q >> 4);
        cp16(smem_base + (YS_OFF + pxl * 68 + (q & 15) * 4) * 4,
             &g_y[bp * MID + q * 4], true);
    }
    #pragma unroll
    for (int it = 0; it < 7; ++it) {
        const int f = tid + 256 * it;            // 0..1791
        const int grp = f / 896;
        const int rem = f - grp * 896;
        const int k = rem / 14, j = rem - (rem / 14) * 14;
        cp16(smem_base + (W2S_OFF + grp * 3584 + k * 56 + j * 4) * 4,
             &g_w2t[(gr0 + grp) * 3584 + k * 56 + j * 4], true);
    }
    asm volatile("cp.async.commit_group;\n" ::: "memory");

    // ---- Phase A group 1: x halo, 16-wide window (completes during GEMM)
    {
        const float* xg = x + (size_t)b * C1 * PP + (size_t)gr0 * 16 * PP;
        #pragma unroll
        for (int it = 0; it < 7; ++it) {
            const int f = tid + 256 * it;        // 0..1791 (= 32ch * 14r * 4j)
            const int ch  = f / 56;              // 0..31
            const int rem = f - ch * 56;
            const int r   = rem >> 2;            // 0..13
            const int j   = rem & 3;             // 0..3
            const int h = h0 + r - 3;
            const int w = w0 - 4 + j * 4;
            const bool ok = (h >= 0 && h < HW && w >= 0 && w <= 52);
            const float* src = ok ? &xg[(size_t)ch * PP + h * HW + w] : xg;
            cp16(smem_base + (XSM_OFF + ch * XC_STR + r * 16 + j * 4) * 4,
                 src, ok);
        }
        asm volatile("cp.async.commit_group;\n" ::: "memory");
    }

    // wait for group 0 only (y + w2); x stays in flight
    asm volatile("cp.async.wait_group 1;\n" ::: "memory");
    __syncthreads();

    // ---- GEMM: warp (grp = wrp>>2, wl = wrp&3): px rows wl*16..+15, 56 o
    float acc[7][4] = {};
    const int grp = wrp >> 2;
    const int pxr = (wrp & 3) * 16 + g;
    const float* w2g = w2s + grp * 3584;
    #pragma unroll
    for (int ks = 0; ks < 8; ++ks) {
        const int kb = ks * 8;
        const uint32_t a0 = __float_as_uint(ys[(pxr    ) * 68 + kb + tig]);
        const uint32_t a1 = __float_as_uint(ys[(pxr + 8) * 68 + kb + tig]);
        const uint32_t a2 = __float_as_uint(ys[(pxr    ) * 68 + kb + tig + 4]);
        const uint32_t a3 = __float_as_uint(ys[(pxr + 8) * 68 + kb + tig + 4]);
        #pragma unroll
        for (int n = 0; n < 7; ++n) {
            const uint32_t b0 = __float_as_uint(w2g[(kb + tig    ) * 56 + n * 8 + g]);
            const uint32_t b1 = __float_as_uint(w2g[(kb + tig + 4) * 56 + n * 8 + g]);
            mma_tf32(acc[n], a0, a1, a2, a3, b0, b1);
        }
    }
    __syncthreads();   // ys/w2s dead; wsm overlays them

    // ---- +sh2, scatter into wsm[grp][o][px] (x cp.async still in flight)
    {
        float* wg = wsm + grp * WSM_STR;
        const int ob = (gr0 + grp) * 49;
        #pragma unroll
        for (int n = 0; n < 7; ++n) {
            const int ola = n * 8 + 2 * tig;
            const int olb = ola + 1;
            if (ola < 49) {
                const float sh = g_sh2[ob + ola];
                wg[ola * 68 + pxr    ] = acc[n][0] + sh;
                wg[ola * 68 + pxr + 8] = acc[n][2] + sh;
            }
            if (olb < 49) {
                const float sh = g_sh2[ob + olb];
                wg[olb * 68 + pxr    ] = acc[n][1] + sh;
                wg[olb * 68 + pxr + 8] = acc[n][3] + sh;
            }
        }
    }
    asm volatile("cp.async.wait_group 0;\n" ::: "memory");
    __syncthreads();

    // ---- involution (f32x2 packed): warp = 1 row x 2 groups x 16 ch
    const int c    = tid & 15;
    const int gsel = (tid >> 4) & 1;
    const int row  = tid >> 5;           // == wrp
    const float* wg = wsm + gsel * WSM_STR;
    const float* xc = xsm + (gsel * 16 + c) * XC_STR;

    ull av2[4] = {0ull, 0ull, 0ull, 0ull};   // (px0,px1)(px2,px3)(px4,px5)(px6,px7)

    #pragma unroll 1
    for (int dy = 0; dy < 7; ++dy) {
        // x row window: 16 floats; xp = even-aligned pairs (free alias),
        // xq = odd-aligned pairs (packed).
        float xr[16];
        #pragma unroll
        for (int q4 = 0; q4 < 4; ++q4)
            *(float4*)&xr[q4 * 4] = *(const float4*)&xc[(row + dy) * 16 + q4 * 4];
        ull xp[7], xq[7];
        #pragma unroll
        for (int k = 1; k < 7; ++k) xp[k] = pack2(xr[2 * k], xr[2 * k + 1]);
        #pragma unroll
        for (int k = 0; k < 7; ++k) xq[k] = pack2(xr[2 * k + 1], xr[2 * k + 2]);

        #pragma unroll
        for (int dx = 0; dx < 7; ++dx) {
            const int kk = dy * 7 + dx;
            // weight pairs: alias the 16B-aligned LDS.128 results as b64 pairs
            const double2 wa = *(const double2*)&wg[kk * 68 + row * 8];
            const double2 wb = *(const double2*)&wg[kk * 68 + row * 8 + 4];
            const ull w01 = __double_as_longlong(wa.x);
            const ull w23 = __double_as_longlong(wa.y);
            const ull w45 = __double_as_longlong(wb.x);
            const ull w67 = __double_as_longlong(wb.y);
            // x index for output j is dx + j + 1:
            // dx even -> odd start  -> xq[dx/2 + j2]
            // dx odd  -> even start -> xp[(dx+1)/2 + j2]
            if ((dx & 1) == 0) {
                const int base = dx >> 1;
                fma2(av2[0], w01, xq[base    ]);
                fma2(av2[1], w23, xq[base + 1]);
                fma2(av2[2], w45, xq[base + 2]);
                fma2(av2[3], w67, xq[base + 3]);
            } else {
                const int base = (dx + 1) >> 1;
                fma2(av2[0], w01, xp[base    ]);
                fma2(av2[1], w23, xp[base + 1]);
                fma2(av2[2], w45, xp[base + 2]);
                fma2(av2[3], w67, xp[base + 3]);
            }
        }
    }

    float* dst = out + ((size_t)b * C1 + (gr0 + gsel) * 16 + c) * PP
                     + (h0 + row) * HW + w0;
    double2 o0, o1;
    o0.x = __longlong_as_double(av2[0]);
    o0.y = __longlong_as_double(av2[1]);
    o1.x = __longlong_as_double(av2[2]);
    o1.y = __longlong_as_double(av2[3]);
    *(double2*)&dst[0] = o0;
    *(double2*)&dst[4] = o1;
}

// ---------------------------------------------------------------------------
extern "C" void kernel_launch(void* const* d_in, const int* in_sizes, int n_in,
                              void* d_out, int out_size)
{
    const float* x   = (const float*)d_in[0];
    const float* w1  = (const float*)d_in[1];
    const float* g1  = (const float*)d_in[2];
    const float* b1  = (const float*)d_in[3];
    const float* mu1 = (const float*)d_in[4];
    const float* v1  = (const float*)d_in[5];
    const float* ap1 = (const float*)d_in[6];
    const float* ap2 = (const float*)d_in[7];
    const float* ab  = (const float*)d_in[8];
    const float* w2  = (const float*)d_in[9];
    const float* g2  = (const float*)d_in[10];
    const float* b2  = (const float*)d_in[11];
    const float* mu2 = (const float*)d_in[12];
    const float* v2  = (const float*)d_in[13];
    float* out = (float*)d_out;

    static bool attr_set = false;
    if (!attr_set) {
        cudaFuncSetAttribute(k23_fused,
            cudaFuncAttributeMaxDynamicSharedMemorySize, POOL_FLOATS * 4);
        attr_set = true;
    }

    k1_conv1_bn_acon<<<588, 128>>>(x, w1, g1, b1, mu1, v1, ap1, ap2, ab,
                                   w2, g2, b2, mu2, v2);

    dim3 grid23(49, 8, BB);
    k23_fused<<<grid23, 256, POOL_FLOATS * 4>>>(x, out);
}

// round 13
// speedup vs baseline: 1.0448x; 1.0448x over previous
#include <cuda_runtime.h>
#include <cstdint>

#define BB 4
#define C1 256
#define MID 64
#define HW 56
#define PP 3136       // 56*56
#define NPX 12544     // BB*PP
#define W2O 784       // 49*16
#define BN_EPS 1e-3f

// Intermediates
__device__ float g_y[NPX * MID];          // pixel-major y[bp][m], tf32-rounded
// w2 repacked for LDS.64 B-frags: [g][ks][o][tig] float2 = (k=ks*8+tig, k=ks*8+tig+4)
__device__ float g_w2q[16 * 3584];        // 3584 floats per group
__device__ float g_sh2[W2O];              // BN2 shift

// ---------------------------------------------------------------------------
__device__ __forceinline__ uint32_t f2tf(float f) {
    uint32_t u;
    asm("cvt.rna.tf32.f32 %0, %1;" : "=r"(u) : "f"(f));
    return u;
}
__device__ __forceinline__ float4 cvt4(float4 v) {
    v.x = __uint_as_float(f2tf(v.x));
    v.y = __uint_as_float(f2tf(v.y));
    v.z = __uint_as_float(f2tf(v.z));
    v.w = __uint_as_float(f2tf(v.w));
    return v;
}
__device__ __forceinline__ void mma_tf32(float* c, uint32_t a0, uint32_t a1,
                                         uint32_t a2, uint32_t a3,
                                         uint32_t b0, uint32_t b1) {
    asm volatile(
        "mma.sync.aligned.m16n8k8.row.col.f32.tf32.tf32.f32 "
        "{%0,%1,%2,%3}, {%4,%5,%6,%7}, {%8,%9}, {%0,%1,%2,%3};\n"
        : "+f"(c[0]), "+f"(c[1]), "+f"(c[2]), "+f"(c[3])
        : "r"(a0), "r"(a1), "r"(a2), "r"(a3), "r"(b0), "r"(b1));
}
__device__ __forceinline__ float aconf(float v, float d12, float p2, float bet) {
    const float d = d12 * v;
    const float sig = 1.0f / (1.0f + __expf(-bet * d));
    return d * sig + p2 * v;
}
// cp.async 16B with zero-fill on !pred
__device__ __forceinline__ void cp16(uint32_t dst, const void* src, bool pred) {
    const int sz = pred ? 16 : 0;
    asm volatile("cp.async.cg.shared.global [%0], [%1], 16, %2;\n"
                 :: "r"(dst), "l"(src), "r"(sz));
}

// ---------------------------------------------------------------------------
// Kernel 1: blocks [0,196): y GEMM (64px x 64m, 256 thr, double-buffered);
//           blocks [196,392): w2q prep + sh2.
// ---------------------------------------------------------------------------
__global__ __launch_bounds__(256) void k1_conv1_bn_acon(
    const float* __restrict__ x, const float* __restrict__ w1,
    const float* __restrict__ g1, const float* __restrict__ b1,
    const float* __restrict__ mu1, const float* __restrict__ v1,
    const float* __restrict__ ap1, const float* __restrict__ ap2,
    const float* __restrict__ ab,
    const float* __restrict__ w2,
    const float* __restrict__ g2, const float* __restrict__ b2,
    const float* __restrict__ mu2, const float* __restrict__ v2)
{
    __shared__ float xs[2][32][72];   // [k][px] pad 72 (mod32=8)
    __shared__ float ws[2][64][36];   // [m][k]  pad 36 (mod32=4)

    const int tid = threadIdx.x;

    if (blockIdx.x >= 196) {
        // ---- prep path: 196 blocks x 4 o-rows, 64 k each
        const int p = blockIdx.x - 196;
        const int k = tid & 63;
        const int o  = p * 4 + (tid >> 6);
        const int g  = o / 49;
        const int ol = o - g * 49;
        const float s = g2[o] * rsqrtf(v2[o] + BN_EPS);
        const float v = __uint_as_float(f2tf(w2[o * MID + k] * s));
        const int ks = k >> 3, kw = k & 7;
        const int tg = kw & 3, hi = kw >> 2;
        g_w2q[g * 3584 + ((ks * 56 + ol) * 4 + tg) * 2 + hi] = v;
        if (k == 0) g_sh2[o] = b2[o] - mu2[o] * s;
        return;
    }

    const int wrp  = tid >> 5;
    const int lane = tid & 31;
    const int g    = lane >> 2;
    const int tig  = lane & 3;
    const int pxg  = wrp & 3;        // 4 px-quarters of 16
    const int nh   = wrp >> 2;       // 2 m-halves of 32

    const int b  = blockIdx.x / 49;
    const int p0 = (blockIdx.x % 49) * 64;
    const float* xb = x + (size_t)b * C1 * PP + p0;

    float4 xv[2], wv[2];

    // prologue: chunk 0
    #pragma unroll
    for (int it = 0; it < 2; ++it) {
        const int f = tid + 256 * it, k = f >> 4, q4 = f & 15;
        xv[it] = *(const float4*)&xb[(size_t)k * PP + q4 * 4];
    }
    #pragma unroll
    for (int it = 0; it < 2; ++it) {
        const int f = tid + 256 * it, m = f >> 3, q = f & 7;
        wv[it] = *(const float4*)&w1[m * C1 + q * 4];
    }
    #pragma unroll
    for (int it = 0; it < 2; ++it) {
        const int f = tid + 256 * it, k = f >> 4, q4 = f & 15;
        *(float4*)&xs[0][k][q4 * 4] = cvt4(xv[it]);
    }
    #pragma unroll
    for (int it = 0; it < 2; ++it) {
        const int f = tid + 256 * it, m = f >> 3, q = f & 7;
        *(float4*)&ws[0][m][q * 4] = cvt4(wv[it]);
    }
    __syncthreads();

    float acc[4][4] = {};
    const int pxr = pxg * 16 + g;

    for (int kc = 0; kc < 8; ++kc) {
        if (kc < 7) {
            const int k0n = (kc + 1) * 32;
            #pragma unroll
            for (int it = 0; it < 2; ++it) {
                const int f = tid + 256 * it, k = f >> 4, q4 = f & 15;
                xv[it] = *(const float4*)&xb[(size_t)(k0n + k) * PP + q4 * 4];
            }
            #pragma unroll
            for (int it = 0; it < 2; ++it) {
                const int f = tid + 256 * it, m = f >> 3, q = f & 7;
                wv[it] = *(const float4*)&w1[m * C1 + k0n + q * 4];
            }
        }
        const int buf = kc & 1;
        #pragma unroll
        for (int ks = 0; ks < 4; ++ks) {
            const int kb = ks * 8;
            const uint32_t a0 = __float_as_uint(xs[buf][kb + tig    ][pxr]);
            const uint32_t a1 = __float_as_uint(xs[buf][kb + tig    ][pxr + 8]);
            const uint32_t a2 = __float_as_uint(xs[buf][kb + tig + 4][pxr]);
            const uint32_t a3 = __float_as_uint(xs[buf][kb + tig + 4][pxr + 8]);
            #pragma unroll
            for (int j = 0; j < 4; ++j) {
                const int m = nh * 32 + j * 8 + g;
                const uint32_t b0 = __float_as_uint(ws[buf][m][kb + tig]);
                const uint32_t b1 = __float_as_uint(ws[buf][m][kb + tig + 4]);
                mma_tf32(acc[j], a0, a1, a2, a3, b0, b1);
            }
        }
        __syncthreads();
        if (kc < 7) {
            const int nb = (kc + 1) & 1;
            #pragma unroll
            for (int it = 0; it < 2; ++it) {
                const int f = tid + 256 * it, k = f >> 4, q4 = f & 15;
                *(float4*)&xs[nb][k][q4 * 4] = cvt4(xv[it]);
            }
            #pragma unroll
            for (int it = 0; it < 2; ++it) {
                const int f = tid + 256 * it, m = f >> 3, q = f & 7;
                *(float4*)&ws[nb][m][q * 4] = cvt4(wv[it]);
            }
            __syncthreads();
        }
    }

    const size_t bp0 = (size_t)b * PP + p0;
    #pragma unroll
    for (int j = 0; j < 4; ++j) {
        const int ma = nh * 32 + j * 8 + 2 * tig;
        const int mb = ma + 1;
        const float sA  = g1[ma] * rsqrtf(v1[ma] + BN_EPS);
        const float shA = b1[ma] - mu1[ma] * sA;
        const float sB  = g1[mb] * rsqrtf(v1[mb] + BN_EPS);
        const float shB = b1[mb] - mu1[mb] * sB;
        const float dA = ap1[ma] - ap2[ma], pA = ap2[ma], bA = ab[ma];
        const float dB = ap1[mb] - ap2[mb], pB = ap2[mb], bB = ab[mb];

        float2 o01, o23;
        o01.x = __uint_as_float(f2tf(aconf(acc[j][0] * sA + shA, dA, pA, bA)));
        o01.y = __uint_as_float(f2tf(aconf(acc[j][1] * sB + shB, dB, pB, bB)));
        o23.x = __uint_as_float(f2tf(aconf(acc[j][2] * sA + shA, dA, pA, bA)));
        o23.y = __uint_as_float(f2tf(aconf(acc[j][3] * sB + shB, dB, pB, bB)));

        *(float2*)&g_y[(bp0 + pxr    ) * MID + ma] = o01;
        *(float2*)&g_y[(bp0 + pxr + 8) * MID + ma] = o23;
    }
}

// ---------------------------------------------------------------------------
// Kernel 23 (fused, v10 = R11 + paired B LDS.64).
// Pool: ys[64][68] | w2s[2][3584] | xsm[32][228]; wsm overlays ys+w2s.
// ---------------------------------------------------------------------------
#define YS_OFF   0
#define W2S_OFF  (64 * 68)                  // 4352
#define XSM_OFF  (W2S_OFF + 2 * 3584)       // 11520
#define XC_STR   228                        // mod 32 = 4 -> conflict-free f4
#define WSM_STR  3332                       // 49*68 per group
#define POOL_FLOATS (XSM_OFF + 32 * XC_STR) // 18816 -> 75264 B

__global__ __launch_bounds__(256, 3) void k23_fused(
    const float* __restrict__ x, float* __restrict__ out)
{
    extern __shared__ float pool[];
    float* ys  = pool + YS_OFF;      // [px][68]
    float* w2s = pool + W2S_OFF;     // [grp][3584] paired layout
    float* xsm = pool + XSM_OFF;     // [ch][14][16] window w0-4..w0+11
    float* wsm = pool + YS_OFF;      // phase B: [grp][49][68]

    const int tid  = threadIdx.x;
    const int wrp  = tid >> 5;
    const int lane = tid & 31;
    const int g    = lane >> 2;
    const int tig  = lane & 3;

    const int t   = blockIdx.x;
    const int gr0 = blockIdx.y * 2;
    const int b   = blockIdx.z;
    const int h0  = (t / 7) * 8;
    const int w0  = (t % 7) * 8;

    const uint32_t smem_base = (uint32_t)__cvta_generic_to_shared(pool);

    // ---- Phase A group 0: y tile + 2 w2q slices
    #pragma unroll
    for (int it = 0; it < 4; ++it) {
        const int f = tid + 256 * it;            // 0..1023
        const int row = f >> 7;
        const int q   = f & 127;
        const size_t bp = (size_t)b * PP + (h0 + row) * HW + w0;
        const int pxl = row * 8 + (q >> 4);
        cp16(smem_base + (YS_OFF + pxl * 68 + (q & 15) * 4) * 4,
             &g_y[bp * MID + q * 4], true);
    }
    #pragma unroll
    for (int it = 0; it < 7; ++it) {
        const int f = tid + 256 * it;            // 0..1791 (= 2*896 f4)
        const int grp = f / 896;
        const int rem = f - grp * 896;
        cp16(smem_base + (W2S_OFF + grp * 3584 + rem * 4) * 4,
             &g_w2q[(gr0 + grp) * 3584 + rem * 4], true);
    }
    asm volatile("cp.async.commit_group;\n" ::: "memory");

    // ---- Phase A group 1: x halo, 16-wide window (completes during GEMM)
    {
        const float* xg = x + (size_t)b * C1 * PP + (size_t)gr0 * 16 * PP;
        #pragma unroll
        for (int it = 0; it < 7; ++it) {
            const int f = tid + 256 * it;        // 0..1791 (= 32ch * 14r * 4j)
            const int ch  = f / 56;              // 0..31
            const int rem = f - ch * 56;
            const int r   = rem >> 2;            // 0..13
            const int j   = rem & 3;             // 0..3
            const int h = h0 + r - 3;
            const int w = w0 - 4 + j * 4;
            const bool ok = (h >= 0 && h < HW && w >= 0 && w <= 52);
            const float* src = ok ? &xg[(size_t)ch * PP + h * HW + w] : xg;
            cp16(smem_base + (XSM_OFF + ch * XC_STR + r * 16 + j * 4) * 4,
                 src, ok);
        }
        asm volatile("cp.async.commit_group;\n" ::: "memory");
    }

    // wait for group 0 only (y + w2); x stays in flight
    asm volatile("cp.async.wait_group 1;\n" ::: "memory");
    __syncthreads();

    // ---- GEMM: warp (grp = wrp>>2, wl = wrp&3): px rows wl*16..+15, 56 o
    float acc[7][4] = {};
    const int grp = wrp >> 2;
    const int pxr = (wrp & 3) * 16 + g;
    const float* w2g = w2s + grp * 3584;
    #pragma unroll
    for (int ks = 0; ks < 8; ++ks) {
        const uint32_t a0 = __float_as_uint(ys[(pxr    ) * 68 + ks * 8 + tig]);
        const uint32_t a1 = __float_as_uint(ys[(pxr + 8) * 68 + ks * 8 + tig]);
        const uint32_t a2 = __float_as_uint(ys[(pxr    ) * 68 + ks * 8 + tig + 4]);
        const uint32_t a3 = __float_as_uint(ys[(pxr + 8) * 68 + ks * 8 + tig + 4]);
        #pragma unroll
        for (int n = 0; n < 7; ++n) {
            const float2 bv = *(const float2*)
                &w2g[((ks * 56 + n * 8 + g) * 4 + tig) * 2];
            mma_tf32(acc[n], a0, a1, a2, a3,
                     __float_as_uint(bv.x), __float_as_uint(bv.y));
        }
    }
    __syncthreads();   // ys/w2s dead; wsm overlays them

    // ---- +sh2, scatter into wsm[grp][o][px] (x cp.async still in flight)
    {
        float* wg = wsm + grp * WSM_STR;
        const int ob = (gr0 + grp) * 49;
        #pragma unroll
        for (int n = 0; n < 7; ++n) {
            const int ola = n * 8 + 2 * tig;
            const int olb = ola + 1;
            if (ola < 49) {
                const float sh = g_sh2[ob + ola];
                wg[ola * 68 + pxr    ] = acc[n][0] + sh;
                wg[ola * 68 + pxr + 8] = acc[n][2] + sh;
            }
            if (olb < 49) {
                const float sh = g_sh2[ob + olb];
                wg[olb * 68 + pxr    ] = acc[n][1] + sh;
                wg[olb * 68 + pxr + 8] = acc[n][3] + sh;
            }
        }
    }
    asm volatile("cp.async.wait_group 0;\n" ::: "memory");
    __syncthreads();

    // ---- involution: warp = 1 row x 2 groups x 16 ch (R11 scalar form)
    const int c    = tid & 15;
    const int gsel = (tid >> 4) & 1;
    const int row  = tid >> 5;           // == wrp
    const float* wg = wsm + gsel * WSM_STR;
    const float* xc = xsm + (gsel * 16 + c) * XC_STR;

    float av[8] = {};
    #pragma unroll 1
    for (int dy = 0; dy < 7; ++dy) {
        float xr[16];
        #pragma unroll
        for (int q4 = 0; q4 < 4; ++q4)
            *(float4*)&xr[q4 * 4] = *(const float4*)&xc[(row + dy) * 16 + q4 * 4];
        #pragma unroll
        for (int dx = 0; dx < 7; ++dx) {
            const int kk = dy * 7 + dx;
            const float4 wa = *(const float4*)&wg[kk * 68 + row * 8];
            const float4 wb = *(const float4*)&wg[kk * 68 + row * 8 + 4];
            const float wj[8] = {wa.x, wa.y, wa.z, wa.w, wb.x, wb.y, wb.z, wb.w};
            #pragma unroll
            for (int j = 0; j < 8; ++j)
                av[j] += wj[j] * xr[dx + j + 1];
        }
    }

    float* dst = out + ((size_t)b * C1 + (gr0 + gsel) * 16 + c) * PP
                     + (h0 + row) * HW + w0;
    *(float4*)&dst[0] = make_float4(av[0], av[1], av[2], av[3]);
    *(float4*)&dst[4] = make_float4(av[4], av[5], av[6], av[7]);
}

// ---------------------------------------------------------------------------
extern "C" void kernel_launch(void* const* d_in, const int* in_sizes, int n_in,
                              void* d_out, int out_size)
{
    const float* x   = (const float*)d_in[0];
    const float* w1  = (const float*)d_in[1];
    const float* g1  = (const float*)d_in[2];
    const float* b1  = (const float*)d_in[3];
    const float* mu1 = (const float*)d_in[4];
    const float* v1  = (const float*)d_in[5];
    const float* ap1 = (const float*)d_in[6];
    const float* ap2 = (const float*)d_in[7];
    const float* ab  = (const float*)d_in[8];
    const float* w2  = (const float*)d_in[9];
    const float* g2  = (const float*)d_in[10];
    const float* b2  = (const float*)d_in[11];
    const float* mu2 = (const float*)d_in[12];
    const float* v2  = (const float*)d_in[13];
    float* out = (float*)d_out;

    static bool attr_set = false;
    if (!attr_set) {
        cudaFuncSetAttribute(k23_fused,
            cudaFuncAttributeMaxDynamicSharedMemorySize, POOL_FLOATS * 4);
        attr_set = true;
    }

    // 196 GEMM blocks + 196 w2-prep blocks
    k1_conv1_bn_acon<<<392, 256>>>(x, w1, g1, b1, mu1, v1, ap1, ap2, ab,
                                   w2, g2, b2, mu2, v2);

    dim3 grid23(49, 8, BB);
    k23_fused<<<grid23, 256, POOL_FLOATS * 4>>>(x, out);
}